// round 2
// baseline (speedup 1.0000x reference)
#include <cuda_runtime.h>
#include <cstdint>

// Problem constants (match reference)
#define NN   25000   // nodes
#define NE   100000  // edges
#define HD   32      // hidden dim
#define NCL  8000    // cliques
#define NA   50000   // node2clique assignments
#define NEC  24000   // clique edges
#define EDIM 8       // edge emb dims
#define NLAY 2

typedef unsigned long long u64;

// ---------------- scratch (device globals; no dynamic allocation) -------------
__device__ float g_x[NN * HD];
__device__ float g_c[NCL * HD];
__device__ float g_h[NE * HD];
__device__ float g_P[(size_t)NN * HD * HD];    // 102.4 MB
__device__ float g_agg[NN * HD];
__device__ float g_m[NN * HD];
__device__ int   g_deg[2 * NN + 2 * NCL];      // [dst | cdst | cid | nid]

// ---------------- f32x2 packed helpers ----------------------------------------
__device__ __forceinline__ u64 pk2(float lo, float hi) {
    u64 r; asm("mov.b64 %0,{%1,%2};" : "=l"(r) : "f"(lo), "f"(hi)); return r;
}
__device__ __forceinline__ u64 fma2(u64 a, u64 b, u64 c) {
    u64 d; asm("fma.rn.f32x2 %0,%1,%2,%3;" : "=l"(d) : "l"(a), "l"(b), "l"(c)); return d;
}

// ---------------- edge MLP + tail-zero -----------------------------------------
// blocks [0, mlpBlocks): warp-per-edge h = relu(ef@w1+b1); remaining blocks zero zptr.
__global__ void k_edge_mlp_zero(int nE, const float* __restrict__ ef,
                                const float* __restrict__ w1, const float* __restrict__ b1,
                                float* __restrict__ hout,
                                float* __restrict__ zptr, int zn, int mlpBlocks) {
    if ((int)blockIdx.x >= mlpBlocks) {
        int i = (blockIdx.x - mlpBlocks) * blockDim.x + threadIdx.x;
        if (i < zn) zptr[i] = 0.f;
        return;
    }
    int e = (blockIdx.x * blockDim.x + threadIdx.x) >> 5;
    int lane = threadIdx.x & 31;
    if (e >= nE) return;
    float ev = (lane < EDIM) ? ef[(size_t)e * EDIM + lane] : 0.f;
    float acc = b1[lane];
#pragma unroll
    for (int j = 0; j < EDIM; j++)
        acc += __shfl_sync(0xffffffffu, ev, j) * w1[j * HD + lane];
    hout[(size_t)e * HD + lane] = fmaxf(acc, 0.f);
}

// ---------------- degree helpers ------------------------------------------------
__global__ void k_zero_deg(int* __restrict__ p, int n) {
    int i = blockIdx.x * blockDim.x + threadIdx.x;
    if (i < n) p[i] = 0;
}
__global__ void k_count2(const int* __restrict__ i1, int* __restrict__ d1, int n1,
                         const int* __restrict__ i2, int* __restrict__ d2, int n2) {
    int i = blockIdx.x * blockDim.x + threadIdx.x;
    if (i < n1) atomicAdd(&d1[i1[i]], 1);
    else if (i - n1 < n2) atomicAdd(&d2[i2[i - n1]], 1);
}
__global__ void k_count1(const int* __restrict__ idx, int* __restrict__ deg, int n) {
    int i = blockIdx.x * blockDim.x + threadIdx.x;
    if (i < n) atomicAdd(&deg[idx[i]], 1);
}

// ---------------- P = X @ T, permutation folded into B load --------------------
// T[i, k*32+o] = w2[k*1024 + i*32 + o].  128x128 tile, 256 thr, 8x8/thread, K=32.
// Inner product uses packed fma.rn.f32x2 (FFMA2): 2 FMA per issue.
__global__ __launch_bounds__(256, 2)
void k_gemmP(const float* __restrict__ X, int nrows,
             const float* __restrict__ w2, float* __restrict__ P) {
    __shared__ float As[HD][128];   // [k][row]
    __shared__ float Bs[HD][128];   // [k][col]
    int tid  = threadIdx.x;
    int row0 = blockIdx.x * 128;
    int col0 = blockIdx.y * 128;

    // load X tile (transposed)
    {
        int r = tid >> 3;
        int q = tid & 7;
        for (int rr = r; rr < 128; rr += 32) {
            int row = row0 + rr;
            float4 v = make_float4(0.f, 0.f, 0.f, 0.f);
            if (row < nrows) v = *(const float4*)(X + (size_t)row * HD + q * 4);
            As[q * 4 + 0][rr] = v.x;
            As[q * 4 + 1][rr] = v.y;
            As[q * 4 + 2][rr] = v.z;
            As[q * 4 + 3][rr] = v.w;
        }
    }
    // load permuted w2 tile: Bs[i][c] = w2[((col0+c)>>5)*1024 + i*32 + ((col0+c)&31)]
    {
        int r = tid >> 5;        // 0..7 (i stride)
        int q = tid & 31;        // float4 col index (c = q*4, same k within float4)
        int C = col0 + q * 4;
        int kcol = C >> 5, o = C & 31;
        for (int kk = r; kk < HD; kk += 8) {
            float4 v = *(const float4*)(w2 + kcol * (HD * HD) + kk * HD + o);
            *(float4*)&Bs[kk][q * 4] = v;
        }
    }
    __syncthreads();

    int tr = (tid >> 4) * 8;
    int tc = (tid & 15) * 8;
    u64 acc[8][4];
#pragma unroll
    for (int a = 0; a < 8; a++)
#pragma unroll
        for (int b = 0; b < 4; b++) acc[a][b] = 0ULL;

#pragma unroll
    for (int k = 0; k < HD; k++) {
        float a[8];
        *(float4*)&a[0] = *(float4*)&As[k][tr];
        *(float4*)&a[4] = *(float4*)&As[k][tr + 4];
        u64 bp[4];
        bp[0] = *(const u64*)&Bs[k][tc];
        bp[1] = *(const u64*)&Bs[k][tc + 2];
        bp[2] = *(const u64*)&Bs[k][tc + 4];
        bp[3] = *(const u64*)&Bs[k][tc + 6];
#pragma unroll
        for (int i = 0; i < 8; i++) {
            u64 ad = pk2(a[i], a[i]);
#pragma unroll
            for (int j = 0; j < 4; j++)
                acc[i][j] = fma2(ad, bp[j], acc[i][j]);
        }
    }

#pragma unroll
    for (int i = 0; i < 8; i++) {
        int row = row0 + tr + i;
        if (row < nrows) {
            u64* dst = (u64*)(P + (size_t)row * (HD * HD) + col0 + tc);
#pragma unroll
            for (int j = 0; j < 4; j++) dst[j] = acc[i][j];
        }
    }
}

// ---------------- per-edge message (+ bias term Q) + scatter-add ----------------
// msg[e,o] = sum_k h[e,k]*P[src,k*32+o] + sum_i x[src,i]*b2[i*32+o]
__global__ void k_edge_msgQ(int nE, const int* __restrict__ src, const int* __restrict__ dst,
                            const float* __restrict__ h, const float* __restrict__ P,
                            const float* __restrict__ x, const float* __restrict__ b2,
                            float* __restrict__ agg) {
    __shared__ float B2s[HD][HD];
    for (int i = threadIdx.x; i < HD * HD; i += blockDim.x)
        B2s[i >> 5][i & 31] = b2[i];
    __syncthreads();

    int e = (blockIdx.x * blockDim.x + threadIdx.x) >> 5;
    int lane = threadIdx.x & 31;
    if (e >= nE) return;
    int s = src[e];
    int d = dst[e];
    float hv = h[(size_t)e * HD + lane];
    float xv = x[(size_t)s * HD + lane];
    const float* Pr = P + (size_t)s * (HD * HD);
    float acc = 0.f;
#pragma unroll
    for (int k = 0; k < HD; k++)
        acc += __shfl_sync(0xffffffffu, hv, k) * Pr[k * HD + lane];
#pragma unroll
    for (int i = 0; i < HD; i++)
        acc += __shfl_sync(0xffffffffu, xv, i) * B2s[i][lane];
    atomicAdd(&agg[(size_t)d * HD + lane], acc);
}

// ---------------- finalize + project + tail-zero --------------------------------
// Xout = relu(agg/deg + Xin@rw + rb);  m = Xout@pw + pb;  optional copy of Xout.
__global__ void k_finalize_proj(const float* __restrict__ Xin, float* __restrict__ Xout,
                                const float* __restrict__ agg, const int* __restrict__ deg,
                                const float* __restrict__ rw, const float* __restrict__ rb,
                                const float* __restrict__ pw, const float* __restrict__ pb,
                                float* __restrict__ m, int nrows, int rowBlocks,
                                float* __restrict__ zptr, int zn,
                                float* __restrict__ copy_out) {
    if ((int)blockIdx.x >= rowBlocks) {
        int i = (blockIdx.x - rowBlocks) * blockDim.x + threadIdx.x;
        if (i < zn) zptr[i] = 0.f;
        return;
    }
    __shared__ float Rs[HD][HD], Pw[HD][HD];
    for (int i = threadIdx.x; i < HD * HD; i += blockDim.x) {
        Rs[i >> 5][i & 31] = rw[i];
        Pw[i >> 5][i & 31] = pw[i];
    }
    __syncthreads();

    int r = (blockIdx.x * blockDim.x + threadIdx.x) >> 5;
    int lane = threadIdx.x & 31;
    if (r >= nrows) return;
    float xv = Xin[(size_t)r * HD + lane];
    float acc = rb[lane] + agg[(size_t)r * HD + lane] / fmaxf((float)deg[r], 1.f);
#pragma unroll
    for (int i = 0; i < HD; i++)
        acc += __shfl_sync(0xffffffffu, xv, i) * Rs[i][lane];
    float xn = fmaxf(acc, 0.f);
    Xout[(size_t)r * HD + lane] = xn;
    if (copy_out) copy_out[(size_t)r * HD + lane] = xn;
    float macc = pb[lane];
#pragma unroll
    for (int i = 0; i < HD; i++)
        macc += __shfl_sync(0xffffffffu, xn, i) * Pw[i][lane];
    m[(size_t)r * HD + lane] = macc;
}

// ---------------- scatter m[from[a]] into agg[to[a]] ----------------------------
__global__ void k_scatter(int nA, const int* __restrict__ from, const int* __restrict__ to,
                          const float* __restrict__ m, float* __restrict__ agg) {
    int a = (blockIdx.x * blockDim.x + threadIdx.x) >> 5;
    int lane = threadIdx.x & 31;
    if (a >= nA) return;
    float v = m[(size_t)from[a] * HD + lane];
    atomicAdd(&agg[(size_t)to[a] * HD + lane], v);
}

// ---------------- out = in + agg/deg (mean residual) ----------------------------
__global__ void k_addmean(const float* __restrict__ in, float* __restrict__ out,
                          const float* __restrict__ agg, const int* __restrict__ deg,
                          int nrows) {
    int i = blockIdx.x * blockDim.x + threadIdx.x;
    if (i >= nrows * HD) return;
    out[i] = in[i] + agg[i] / fmaxf((float)deg[i >> 5], 1.f);
}

// ================================================================================
static inline int cdiv(int a, int b) { return (a + b - 1) / b; }

extern "C" void kernel_launch(void* const* d_in, const int* in_sizes, int n_in,
                              void* d_out, int out_size) {
    const float* node_features   = (const float*)d_in[0];
    const int*   edge_index      = (const int*)d_in[1];
    const float* edge_features   = (const float*)d_in[2];
    const float* clique_features = (const float*)d_in[3];
    const int*   n2c_index       = (const int*)d_in[4];
    const int*   cedge_index     = (const int*)d_in[5];
    const float* cedge_features  = (const float*)d_in[6];
    const float* nn1_w  = (const float*)d_in[7];
    const float* nn1_b  = (const float*)d_in[8];
    const float* nn2_w  = (const float*)d_in[9];
    const float* nn2_b  = (const float*)d_in[10];
    const float* root_w = (const float*)d_in[11];
    const float* root_b = (const float*)d_in[12];
    const float* n2c_w  = (const float*)d_in[13];
    const float* n2c_b  = (const float*)d_in[14];
    const float* cnn1_w = (const float*)d_in[15];
    const float* cnn1_b = (const float*)d_in[16];
    const float* cnn2_w = (const float*)d_in[17];
    const float* cnn2_b = (const float*)d_in[18];
    const float* croot_w = (const float*)d_in[19];
    const float* croot_b = (const float*)d_in[20];
    const float* c2n_w  = (const float*)d_in[21];
    const float* c2n_b  = (const float*)d_in[22];
    float* out = (float*)d_out;

    const int* src  = edge_index;
    const int* dst  = edge_index + NE;
    const int* nid  = n2c_index;
    const int* cid  = n2c_index + NA;
    const int* csrc = cedge_index;
    const int* cdst = cedge_index + NEC;

    float *x, *c, *h, *P, *agg, *m;
    int* deg;
    cudaGetSymbolAddress((void**)&x, g_x);
    cudaGetSymbolAddress((void**)&c, g_c);
    cudaGetSymbolAddress((void**)&h, g_h);
    cudaGetSymbolAddress((void**)&P, g_P);
    cudaGetSymbolAddress((void**)&agg, g_agg);
    cudaGetSymbolAddress((void**)&m, g_m);
    cudaGetSymbolAddress((void**)&deg, g_deg);
    int* deg_dst  = deg;
    int* deg_cdst = deg + NN;
    int* deg_cid  = deg + NN + NCL;
    int* deg_nid  = deg + NN + 2 * NCL;

    const int TB = 256;
    const int DEG_N = 2 * NN + 2 * NCL;
    dim3 gemmGridN(cdiv(NN, 128), 8);
    dim3 gemmGridC(cdiv(NCL, 128), 8);
    int mlpB_n = cdiv(NE * 32, TB);
    int mlpB_c = cdiv(NEC * 32, TB);
    int zB_n = cdiv(NN * HD, TB);   // zero-tail blocks for NN*HD
    int zB_c = cdiv(NCL * HD, TB);
    int finB_n = cdiv(NN * 32, TB); // finalize row blocks
    int finB_c = cdiv(NCL * 32, TB);

    // ---------- layer 0, node conv (ordered so launch #6 = k_gemmP for ncu) -----
    // 1: edge mlp + zero agg(NN*HD)
    k_edge_mlp_zero<<<mlpB_n + zB_n, TB>>>(NE, edge_features, nn1_w, nn1_b, h,
                                           agg, NN * HD, mlpB_n);
    // 2-5: degree setup
    k_zero_deg<<<cdiv(DEG_N, TB), TB>>>(deg, DEG_N);
    k_count2<<<cdiv(NE + NEC, TB), TB>>>(dst, deg_dst, NE, cdst, deg_cdst, NEC);
    k_count1<<<cdiv(NA, TB), TB>>>(nid, deg_nid, NA);
    k_count1<<<cdiv(NA, TB), TB>>>(cid, deg_cid, NA);
    // 6: gemmP (PROFILED by ncu -s 5 -c 1)
    k_gemmP<<<gemmGridN, 256>>>(node_features, NN, nn2_w, P);
    // 7: edge messages + Q + scatter
    k_edge_msgQ<<<mlpB_n, TB>>>(NE, src, dst, h, P, node_features, nn2_b, agg);
    // 8: finalize x + project m = x@n2c; zero agg for clique scatter
    k_finalize_proj<<<finB_n + zB_c, TB>>>(node_features, x, agg, deg_dst,
                                           root_w, root_b, n2c_w, n2c_b,
                                           m, NN, finB_n, agg, 0, nullptr);
    // careful: agg is both consumed and re-zeroed above — NOT allowed in same kernel.
    // (zero handled below instead; zn=0 above disables the tail's effect)

    // 8b: zero agg (NCL*HD) then 9: scatter node->clique, 10: c = cf + mean
    k_edge_mlp_zero<<<zB_c, TB>>>(0, nullptr, nullptr, nullptr, nullptr,
                                  agg, NCL * HD, 0);
    k_scatter<<<cdiv(NA * 32, TB), TB>>>(NA, nid, cid, m, agg);
    k_addmean<<<cdiv(NCL * HD, TB), TB>>>(clique_features, c, agg, deg_cid, NCL);

    // ---------- layer 0, clique conv ----------
    k_edge_mlp_zero<<<mlpB_c + zB_c, TB>>>(NEC, cedge_features, cnn1_w, cnn1_b, h,
                                           agg, NCL * HD, mlpB_c);
    k_gemmP<<<gemmGridC, 256>>>(c, NCL, cnn2_w, P);
    k_edge_msgQ<<<mlpB_c, TB>>>(NEC, csrc, cdst, h, P, c, cnn2_b, agg);
    k_finalize_proj<<<finB_c, TB>>>(c, c, agg, deg_cdst,
                                    croot_w, croot_b, c2n_w, c2n_b,
                                    m, NCL, finB_c, agg, 0, nullptr);
    k_edge_mlp_zero<<<zB_n, TB>>>(0, nullptr, nullptr, nullptr, nullptr,
                                  agg, NN * HD, 0);
    k_scatter<<<cdiv(NA * 32, TB), TB>>>(NA, cid, nid, m, agg);
    k_addmean<<<cdiv(NN * HD, TB), TB>>>(x, x, agg, deg_nid, NN);

    // ---------- layer 1, node conv ----------
    k_edge_mlp_zero<<<mlpB_n + zB_n, TB>>>(NE, edge_features, nn1_w + EDIM * HD,
                                           nn1_b + HD, h, agg, NN * HD, mlpB_n);
    k_gemmP<<<gemmGridN, 256>>>(x, NN, nn2_w + HD * HD * HD, P);
    k_edge_msgQ<<<mlpB_n, TB>>>(NE, src, dst, h, P, x, nn2_b + HD * HD, agg);
    k_finalize_proj<<<finB_n, TB>>>(x, x, agg, deg_dst,
                                    root_w + HD * HD, root_b + HD,
                                    n2c_w + HD * HD, n2c_b + HD,
                                    m, NN, finB_n, agg, 0, nullptr);
    k_edge_mlp_zero<<<zB_c, TB>>>(0, nullptr, nullptr, nullptr, nullptr,
                                  agg, NCL * HD, 0);
    k_scatter<<<cdiv(NA * 32, TB), TB>>>(NA, nid, cid, m, agg);
    k_addmean<<<cdiv(NCL * HD, TB), TB>>>(c, c, agg, deg_cid, NCL);

    // ---------- layer 1, clique conv ----------
    k_edge_mlp_zero<<<mlpB_c + zB_c, TB>>>(NEC, cedge_features, cnn1_w + EDIM * HD,
                                           cnn1_b + HD, h, agg, NCL * HD, mlpB_c);
    k_gemmP<<<gemmGridC, 256>>>(c, NCL, cnn2_w + HD * HD * HD, P);
    k_edge_msgQ<<<mlpB_c, TB>>>(NEC, csrc, cdst, h, P, c, cnn2_b + HD * HD, agg);
    // final c: also copy straight into output region
    k_finalize_proj<<<finB_c, TB>>>(c, c, agg, deg_cdst,
                                    croot_w + HD * HD, croot_b + HD,
                                    c2n_w + HD * HD, c2n_b + HD,
                                    m, NCL, finB_c, agg, 0, out + (size_t)NN * HD);
    k_edge_mlp_zero<<<zB_n, TB>>>(0, nullptr, nullptr, nullptr, nullptr,
                                  agg, NN * HD, 0);
    k_scatter<<<cdiv(NA * 32, TB), TB>>>(NA, cid, nid, m, agg);
    // final x written directly to output
    k_addmean<<<cdiv(NN * HD, TB), TB>>>(x, out, agg, deg_nid, NN);
}